// round 2
// baseline (speedup 1.0000x reference)
#include <cuda_runtime.h>

// HMLoss: 4-region histogram-matching L1 loss, H=W=2048.
// R2: single fused data pass. Per src region/channel we accumulate BOTH the
// CDF histogram (bins floor(v*256/255)) and the loss moments over floor-bins
// (cnt2[k], sum2[k] = sum of v). Since tbl[k] is constant per floor-bin and
// sign(v - tbl[k]) is uniform within a bin, sum|v-tbl| = |sum2 - tbl*cnt2|
// exactly -- the entire second image pass is eliminated.

#define NPIX 4194304   // 2048*2048
#define NQ   1048576   // NPIX/4
#define NB   256

__device__ unsigned int g_hsrc[12 * NB];  // src CDF hists  [region*3+c][bin]
__device__ unsigned int g_htar[12 * NB];  // tar CDF hists
__device__ unsigned int g_cnt2[12 * NB];  // floor-bin counts (src, loss side)
__device__ double       g_sum2[12 * NB];  // floor-bin value sums
__device__ double       g_acc;

#define MFACE_S ((1u<<1)|(1u<<7)|(1u<<8)|(1u<<10)|(1u<<11)|(1u<<14))
#define MFACE_T ((1u<<1)|(1u<<7)|(1u<<8)|(1u<<10)|(1u<<14))
#define MHAIR   (1u<<17)
#define MEL     ((1u<<2)|(1u<<4))
#define MER     ((1u<<3)|(1u<<5))

// floor for x in [0, 2^23): round-toward-zero add of 2^23, take mantissa bits.
__device__ __forceinline__ int floor_pos(float x) {
    return __float_as_int(__fadd_rz(x, 8388608.0f)) & 0x7FFFFF;
}

// de_norm: clip((x+1)/2, 0, 1) * 255
__device__ __forceinline__ float denorm(float x) {
    return __saturatef(fmaf(x, 0.5f, 0.5f)) * 255.0f;
}

// region id from a label-bit; label sets are disjoint.
__device__ __forceinline__ int reg_of(unsigned bit, unsigned mface) {
    int r = -1;
    if (bit & MER)   r = 3;
    if (bit & MEL)   r = 2;
    if (bit & MHAIR) r = 1;
    if (bit & mface) r = 0;
    return r;
}

// ---------------------------------------------------------------- K0: zero
__global__ void zero_kernel() {
    int i = blockIdx.x * 256 + threadIdx.x;
    if (i < 12 * NB) {
        g_hsrc[i] = 0u; g_htar[i] = 0u; g_cnt2[i] = 0u; g_sum2[i] = 0.0;
    }
    if (i == 0) g_acc = 0.0;
}

// ---------------------------------------------------------------- K1: fused pass
__device__ __forceinline__ void src_chan(float v, unsigned* s_hsrc,
                                         unsigned* s_cnt2, float* s_sum2, int base)
{
    const float CB = 256.0f / 255.0f;
    int i = min(floor_pos(v), 255);        // floor-bin (loss lookup index)
    int b = min(floor_pos(v * CB), 255);   // CDF histogram bin
    atomicAdd(&s_hsrc[base + b], 1u);
    atomicAdd(&s_cnt2[base + i], 1u);
    atomicAdd(&s_sum2[base + i], v);
}

__device__ __forceinline__ void fused_px(int la, int lb,
                                         float fa, float fb, float fc,
                                         float ra, float rb, float rc,
                                         unsigned* s_hsrc, unsigned* s_htar,
                                         unsigned* s_cnt2, float* s_sum2)
{
    const float CB = 256.0f / 255.0f;
    unsigned ab = 1u << la;
    unsigned bb = 1u << lb;

    // ---- src side: CDF hist + loss moments over mask_A regions
    int rs = reg_of(ab, MFACE_S);
    if (rs >= 0) {
        int base = rs * 3 * NB;
        src_chan(denorm(fa), s_hsrc, s_cnt2, s_sum2, base);
        src_chan(denorm(fb), s_hsrc, s_cnt2, s_sum2, base + NB);
        src_chan(denorm(fc), s_hsrc, s_cnt2, s_sum2, base + 2 * NB);
    }

    // ---- tar side: face mask = (mb in faceset) + (ma == 11); value can be 2.
    int rt = reg_of(bb, MFACE_T);
    int faceval = (rt == 0 ? 1 : 0) + (la == 11 ? 1 : 0);
    if (faceval > 0 || rt > 0) {
        float scale = (faceval == 2) ? 2.0f : 1.0f;  // faceval==2 implies rt==0
        float v0 = denorm(ra) * scale, v1 = denorm(rb) * scale, v2 = denorm(rc) * scale;
        int b0 = min(floor_pos(v0 * CB), 255);
        int b1 = min(floor_pos(v1 * CB), 255);
        int b2 = min(floor_pos(v2 * CB), 255);
        if (faceval > 0) {
            atomicAdd(&s_htar[b0], 1u);
            atomicAdd(&s_htar[NB + b1], 1u);
            atomicAdd(&s_htar[2 * NB + b2], 1u);
        }
        if (rt > 0) {
            int base = rt * 3 * NB;
            atomicAdd(&s_htar[base + b0], 1u);
            atomicAdd(&s_htar[base + NB + b1], 1u);
            atomicAdd(&s_htar[base + 2 * NB + b2], 1u);
        }
    }
}

__global__ void __launch_bounds__(512, 2) fused_kernel(
    const float4* __restrict__ fake, const float4* __restrict__ refb,
    const int4* __restrict__ ma, const int4* __restrict__ mb)
{
    __shared__ unsigned s_hsrc[12 * NB];
    __shared__ unsigned s_htar[12 * NB];
    __shared__ unsigned s_cnt2[12 * NB];
    __shared__ float    s_sum2[12 * NB];
    for (int i = threadIdx.x; i < 12 * NB; i += 512) {
        s_hsrc[i] = 0u; s_htar[i] = 0u; s_cnt2[i] = 0u; s_sum2[i] = 0.0f;
    }
    __syncthreads();

    int stride = gridDim.x * 512;
    for (int q = blockIdx.x * 512 + threadIdx.x; q < NQ; q += stride) {
        int4   a4 = ma[q],  b4 = mb[q];
        float4 f0 = fake[q], f1 = fake[q + NQ], f2 = fake[q + 2 * NQ];
        float4 r0 = refb[q], r1 = refb[q + NQ], r2 = refb[q + 2 * NQ];
        fused_px(a4.x, b4.x, f0.x, f1.x, f2.x, r0.x, r1.x, r2.x, s_hsrc, s_htar, s_cnt2, s_sum2);
        fused_px(a4.y, b4.y, f0.y, f1.y, f2.y, r0.y, r1.y, r2.y, s_hsrc, s_htar, s_cnt2, s_sum2);
        fused_px(a4.z, b4.z, f0.z, f1.z, f2.z, r0.z, r1.z, r2.z, s_hsrc, s_htar, s_cnt2, s_sum2);
        fused_px(a4.w, b4.w, f0.w, f1.w, f2.w, r0.w, r1.w, r2.w, s_hsrc, s_htar, s_cnt2, s_sum2);
    }
    __syncthreads();

    for (int i = threadIdx.x; i < 12 * NB; i += 512) {
        unsigned v;
        v = s_hsrc[i]; if (v) atomicAdd(&g_hsrc[i], v);
        v = s_htar[i]; if (v) atomicAdd(&g_htar[i], v);
        v = s_cnt2[i]; if (v) atomicAdd(&g_cnt2[i], v);
        float f = s_sum2[i]; if (f != 0.0f) atomicAdd(&g_sum2[i], (double)f);
    }
}

// ---------------------------------------------------------------- K2: CDFs + tables + loss
// One block per (region, channel). Sequential cumsum matches reference order.
__global__ void table_loss_kernel()
{
    __shared__ unsigned cs[NB], ct[NB];
    __shared__ float cd[NB], ca[NB];
    __shared__ double wsum[8];
    int rc = blockIdx.x;            // 0..11 = region*3 + c
    int t = threadIdx.x;            // 256 threads

    cs[t] = g_hsrc[rc * NB + t];
    ct[t] = g_htar[rc * NB + t];
    __syncthreads();

    if (t < 2) {
        const unsigned* h = (t == 0) ? cs : ct;
        float tot = 0.0f;
        for (int k = 0; k < NB; k++) tot += (float)h[k];   // exact (integer < 2^24)
        tot = fmaxf(tot, 1.0f);
        float run = 0.0f;
        float* dst = (t == 0) ? cd : ca;
        for (int k = 0; k < NB; k++) { run += (float)h[k] / tot; dst[k] = run; }
    }
    __syncthreads();

    // table[i] = first j in 1..255 with ca[j-1] <= cd[i] <= ca[j], else i.
    float dc = cd[t];
    int tbl = t;
    for (int k = 0; k < 255; k++) {
        if (dc >= ca[k] && dc <= ca[k + 1]) { tbl = k + 1; break; }
    }
    if (t == 0)   tbl = 0;
    if (t == 255) tbl = 255;

    // loss contribution of floor-bin t:  sum_{v in bin} |v - tbl| = |sum2 - tbl*cnt2|
    double term = fabs(g_sum2[rc * NB + t]
                       - (double)tbl * (double)g_cnt2[rc * NB + t]);

    #pragma unroll
    for (int off = 16; off > 0; off >>= 1)
        term += __shfl_down_sync(0xffffffffu, term, off);
    int lane = t & 31, wid = t >> 5;
    if (lane == 0) wsum[wid] = term;
    __syncthreads();
    if (t == 0) {
        double s = 0.0;
        #pragma unroll
        for (int i = 0; i < 8; i++) s += wsum[i];
        atomicAdd(&g_acc, s);
    }
}

// ---------------------------------------------------------------- K3: finalize
__global__ void final_kernel(float* out) {
    // loss = 0.1 * total_abs_sum / (3*H*W); all four lambdas are 0.1
    out[0] = (float)(g_acc * (0.1 / 12582912.0));
}

// ---------------------------------------------------------------- launch
extern "C" void kernel_launch(void* const* d_in, const int* in_sizes, int n_in,
                              void* d_out, int out_size)
{
    (void)in_sizes; (void)n_in; (void)out_size;
    const float4* fake = (const float4*)d_in[0];
    const float4* refb = (const float4*)d_in[1];
    const int4*   ma   = (const int4*)d_in[2];
    const int4*   mb   = (const int4*)d_in[3];
    float* out = (float*)d_out;

    zero_kernel      <<<12, 256>>>();
    fused_kernel     <<<296, 512>>>(fake, refb, ma, mb);
    table_loss_kernel<<<12, 256>>>();
    final_kernel     <<<1, 1>>>(out);
}

// round 3
// speedup vs baseline: 1.2270x; 1.2270x over previous
#include <cuda_runtime.h>

// HMLoss: 4-region histogram-matching L1 loss, H=W=2048.
// R3: R1 two-pass structure, occupancy-tuned.
//   K0 zero -> K1 hist (592 blk x 512 thr, 4/SM, 64 warps)
//   -> K2 tables (12 blk) -> K3 loss (1184 blk x 256 thr, 8/SM) + inline finalize.

#define NPIX 4194304   // 2048*2048
#define NQ   1048576   // NPIX/4
#define NB   256
#define NHIST 24       // 4 regions x {src,tar} x 3 channels

__device__ unsigned int g_hist[NHIST * NB];
__device__ float        g_tables[12 * NB];   // [region*3+c][256]
__device__ double       g_acc;
__device__ unsigned int g_ticket;

#define MFACE_S ((1u<<1)|(1u<<7)|(1u<<8)|(1u<<10)|(1u<<11)|(1u<<14))
#define MFACE_T ((1u<<1)|(1u<<7)|(1u<<8)|(1u<<10)|(1u<<14))
#define MHAIR   (1u<<17)
#define MEL     ((1u<<2)|(1u<<4))
#define MER     ((1u<<3)|(1u<<5))

#define LOSS_GRID 1184

// floor for x in [0, 2^23): round-toward-zero add of 2^23, take mantissa bits.
__device__ __forceinline__ int floor_pos(float x) {
    return __float_as_int(__fadd_rz(x, 8388608.0f)) & 0x7FFFFF;
}

// de_norm: clip((x+1)/2, 0, 1) * 255
__device__ __forceinline__ float denorm(float x) {
    return __saturatef(fmaf(x, 0.5f, 0.5f)) * 255.0f;
}

// region id from a label-bit; label sets are disjoint.
__device__ __forceinline__ int reg_of(unsigned bit, unsigned mface) {
    int r = -1;
    if (bit & MER)   r = 3;
    if (bit & MEL)   r = 2;
    if (bit & MHAIR) r = 1;
    if (bit & mface) r = 0;
    return r;
}

// ---------------------------------------------------------------- K0: zero
__global__ void zero_kernel() {
    int i = blockIdx.x * 256 + threadIdx.x;
    if (i < NHIST * NB) g_hist[i] = 0u;
    if (i == 0) { g_acc = 0.0; g_ticket = 0u; }
}

// ---------------------------------------------------------------- K1: histograms
__device__ __forceinline__ void hist_px(int la, int lb,
                                        float fa, float fb, float fc,
                                        float ra, float rb, float rc,
                                        unsigned int* sh)
{
    const float CB = 256.0f / 255.0f;
    unsigned ab = 1u << la;
    unsigned bb = 1u << lb;

    // ---- src side
    int rs = reg_of(ab, MFACE_S);
    if (rs >= 0) {
        unsigned base = (unsigned)rs * (6 * NB);
        int b0 = min(floor_pos(denorm(fa) * CB), 255);
        int b1 = min(floor_pos(denorm(fb) * CB), 255);
        int b2 = min(floor_pos(denorm(fc) * CB), 255);
        atomicAdd(&sh[base          + b0], 1u);
        atomicAdd(&sh[base +     NB + b1], 1u);
        atomicAdd(&sh[base + 2 * NB + b2], 1u);
    }

    // ---- tar side: face mask = (mb in faceset) + (ma == 11); value can be 2.
    int rt = reg_of(bb, MFACE_T);
    int faceval = (rt == 0 ? 1 : 0) + (la == 11 ? 1 : 0);
    if (faceval > 0 || rt > 0) {
        float scale = (faceval == 2) ? 2.0f : 1.0f;  // faceval==2 implies rt==0
        int b0 = min(floor_pos(denorm(ra) * scale * CB), 255);
        int b1 = min(floor_pos(denorm(rb) * scale * CB), 255);
        int b2 = min(floor_pos(denorm(rc) * scale * CB), 255);
        if (faceval > 0) {
            unsigned base = 3 * NB;               // region 0, tar
            atomicAdd(&sh[base          + b0], 1u);
            atomicAdd(&sh[base +     NB + b1], 1u);
            atomicAdd(&sh[base + 2 * NB + b2], 1u);
        }
        if (rt > 0) {
            unsigned base = (unsigned)rt * (6 * NB) + 3 * NB;
            atomicAdd(&sh[base          + b0], 1u);
            atomicAdd(&sh[base +     NB + b1], 1u);
            atomicAdd(&sh[base + 2 * NB + b2], 1u);
        }
    }
}

__global__ void __launch_bounds__(512, 4) hist_kernel(
    const float4* __restrict__ fake, const float4* __restrict__ refb,
    const int4* __restrict__ ma, const int4* __restrict__ mb)
{
    __shared__ unsigned int sh[NHIST * NB];   // 24 KB -> 4 blocks/SM
    for (int i = threadIdx.x; i < NHIST * NB; i += 512) sh[i] = 0u;
    __syncthreads();

    int stride = gridDim.x * 512;
    for (int q = blockIdx.x * 512 + threadIdx.x; q < NQ; q += stride) {
        int4   a4 = ma[q],  b4 = mb[q];
        float4 f0 = fake[q], f1 = fake[q + NQ], f2 = fake[q + 2 * NQ];
        float4 r0 = refb[q], r1 = refb[q + NQ], r2 = refb[q + 2 * NQ];
        hist_px(a4.x, b4.x, f0.x, f1.x, f2.x, r0.x, r1.x, r2.x, sh);
        hist_px(a4.y, b4.y, f0.y, f1.y, f2.y, r0.y, r1.y, r2.y, sh);
        hist_px(a4.z, b4.z, f0.z, f1.z, f2.z, r0.z, r1.z, r2.z, sh);
        hist_px(a4.w, b4.w, f0.w, f1.w, f2.w, r0.w, r1.w, r2.w, sh);
    }
    __syncthreads();
    for (int i = threadIdx.x; i < NHIST * NB; i += 512) {
        unsigned v = sh[i];
        if (v) atomicAdd(&g_hist[i], v);
    }
}

// ---------------------------------------------------------------- K2: CDFs + tables
__global__ void table_kernel()
{
    __shared__ unsigned int cnt[2][NB];
    __shared__ float cd[NB], ca[NB];
    int rc = blockIdx.x;            // 0..11 = region*3 + c
    int region = rc / 3, c = rc % 3;
    int t = threadIdx.x;            // 256 threads

    cnt[0][t] = g_hist[(region * 6 + c)     * NB + t];   // src
    cnt[1][t] = g_hist[(region * 6 + 3 + c) * NB + t];   // tar
    __syncthreads();

    if (t < 2) {
        float tot = 0.0f;
        for (int k = 0; k < NB; k++) tot += (float)cnt[t][k];   // exact (< 2^24)
        tot = fmaxf(tot, 1.0f);
        float run = 0.0f;
        float* dst = (t == 0) ? cd : ca;
        for (int k = 0; k < NB; k++) { run += (float)cnt[t][k] / tot; dst[k] = run; }
    }
    __syncthreads();

    // table[i] = first j in 1..255 with ca[j-1] <= cd[i] <= ca[j], else i.
    float dc = cd[t];
    int tbl = t;
    for (int k = 0; k < 255; k++) {
        if (dc >= ca[k] && dc <= ca[k + 1]) { tbl = k + 1; break; }
    }
    if (t == 0)   tbl = 0;
    if (t == 255) tbl = 255;
    g_tables[rc * NB + t] = (float)tbl;
}

// ---------------------------------------------------------------- K3: L1 loss (+ finalize)
__device__ __forceinline__ float loss_px(int la, float fa, float fb, float fc,
                                         const float* tbl)
{
    unsigned ab = 1u << la;
    int rs = reg_of(ab, MFACE_S);
    float s = 0.0f;
    if (rs >= 0) {
        const float* tb = tbl + rs * 3 * NB;
        float v0 = denorm(fa), v1 = denorm(fb), v2 = denorm(fc);
        int i0 = min(floor_pos(v0), 255);
        int i1 = min(floor_pos(v1), 255);
        int i2 = min(floor_pos(v2), 255);
        s = fabsf(v0 - tb[i0]) + fabsf(v1 - tb[NB + i1]) + fabsf(v2 - tb[2 * NB + i2]);
    }
    return s;
}

__global__ void __launch_bounds__(256, 8) loss_kernel(
    const float4* __restrict__ fake, const int4* __restrict__ ma, float* out)
{
    __shared__ float tbl[12 * NB];   // 12 KB -> 8 blocks/SM
    __shared__ float wsum[8];
    for (int i = threadIdx.x; i < 12 * NB; i += 256) tbl[i] = g_tables[i];
    __syncthreads();

    float acc = 0.0f;
    int stride = gridDim.x * 256;
    for (int q = blockIdx.x * 256 + threadIdx.x; q < NQ; q += stride) {
        int4   a4 = ma[q];
        float4 f0 = fake[q], f1 = fake[q + NQ], f2 = fake[q + 2 * NQ];
        acc += loss_px(a4.x, f0.x, f1.x, f2.x, tbl);
        acc += loss_px(a4.y, f0.y, f1.y, f2.y, tbl);
        acc += loss_px(a4.z, f0.z, f1.z, f2.z, tbl);
        acc += loss_px(a4.w, f0.w, f1.w, f2.w, tbl);
    }

    #pragma unroll
    for (int off = 16; off > 0; off >>= 1)
        acc += __shfl_down_sync(0xffffffffu, acc, off);
    int lane = threadIdx.x & 31, wid = threadIdx.x >> 5;
    if (lane == 0) wsum[wid] = acc;
    __syncthreads();
    if (threadIdx.x == 0) {
        float s = 0.0f;
        #pragma unroll
        for (int i = 0; i < 8; i++) s += wsum[i];
        atomicAdd(&g_acc, (double)s);
        __threadfence();
        unsigned t = atomicAdd(&g_ticket, 1u);
        if (t == (unsigned)(gridDim.x - 1)) {
            // all blocks' g_acc adds are visible (fence + acquire via atomic chain)
            double total = *((volatile double*)&g_acc);
            out[0] = (float)(total * (0.1 / 12582912.0));  // 0.1/(3*H*W)
        }
    }
}

// ---------------------------------------------------------------- launch
extern "C" void kernel_launch(void* const* d_in, const int* in_sizes, int n_in,
                              void* d_out, int out_size)
{
    (void)in_sizes; (void)n_in; (void)out_size;
    const float4* fake = (const float4*)d_in[0];
    const float4* refb = (const float4*)d_in[1];
    const int4*   ma   = (const int4*)d_in[2];
    const int4*   mb   = (const int4*)d_in[3];
    float* out = (float*)d_out;

    zero_kernel <<<24, 256>>>();
    hist_kernel <<<592, 512>>>(fake, refb, ma, mb);
    table_kernel<<<12, 256>>>();
    loss_kernel <<<LOSS_GRID, 256>>>(fake, ma, out);
}